// round 1
// baseline (speedup 1.0000x reference)
#include <cuda_runtime.h>
#include <math.h>

// ---------------- problem constants ----------------
#define Bq      32
#define Hh      56
#define Wd      56
#define Cc      192
#define WSZ     7
#define SSH     3
#define NHEADS  6
#define HDm     32
#define NT      49          // tokens per window
#define NWIN    64          // windows per image
#define HIDDEN  768
#define M_TOK   (Bq*Hh*Wd)  // 100352
#define NWINTOT (Bq*NWIN)   // 2048
#define SCALEQ  0.17677669529663687f
#define EPSLN   1e-5f

// ---------------- scratch (device globals; allocation is forbidden) ----------
__device__ __align__(256) float g_xw    [M_TOK * Cc];                     // LN1 + shift + window-partition
__device__ __align__(256) float g_qkv   [3u * NWINTOT * NHEADS * NT * HDm];
__device__ __align__(256) float g_attn  [M_TOK * Cc];                     // attention output, windowed rows
__device__ __align__(256) float g_xres  [M_TOK * Cc];                     // x + attn (token order)
__device__ __align__(256) float g_h2    [M_TOK * Cc];                     // LN2
__device__ __align__(256) float g_hidden[M_TOK * HIDDEN];                 // fc1+gelu

// ---------------- LayerNorm (warp per row) ----------------
// WINDOWED=1: output row r is a windowed (shifted) row; read from the mapped source token.
// WINDOWED=0: identity rows.
template<int WINDOWED>
__global__ void __launch_bounds__(256) ln_kernel(const float* __restrict__ x,
                                                 const float* __restrict__ gma,
                                                 const float* __restrict__ bta,
                                                 float* __restrict__ out) {
    int row  = blockIdx.x * 8 + (threadIdx.x >> 5);
    int lane = threadIdx.x & 31;
    if (row >= M_TOK) return;

    int src;
    if (WINDOWED) {
        int win = row / NT, n = row % NT;
        int b = win >> 6, wrem = win & 63;
        int i = (wrem >> 3) * WSZ + n / WSZ;
        int j = (wrem & 7)  * WSZ + n % WSZ;
        int h = i + SSH; if (h >= Hh) h -= Hh;
        int w = j + SSH; if (w >= Wd) w -= Wd;
        src = b * (Hh * Wd) + h * Wd + w;
    } else {
        src = row;
    }

    const float* xp = x + (size_t)src * Cc;
    float v[6];
    float s = 0.f, s2 = 0.f;
#pragma unroll
    for (int t = 0; t < 6; t++) {
        v[t] = xp[lane + 32 * t];
        s  += v[t];
        s2 += v[t] * v[t];
    }
#pragma unroll
    for (int o = 16; o > 0; o >>= 1) {
        s  += __shfl_xor_sync(0xFFFFFFFFu, s,  o);
        s2 += __shfl_xor_sync(0xFFFFFFFFu, s2, o);
    }
    float m   = s * (1.0f / Cc);
    float var = s2 * (1.0f / Cc) - m * m;
    float r   = rsqrtf(var + EPSLN);

    float* op = out + (size_t)row * Cc;
#pragma unroll
    for (int t = 0; t < 6; t++) {
        int c = lane + 32 * t;
        op[c] = (v[t] - m) * r * gma[c] + bta[c];
    }
}

// ---------------- tiled fp32 GEMM, 64x64x16, 256 threads, 4x4 microtile ------
// C = A[M x K] * W[K x N] + bias, with epilogue variants:
//  EPI 0: QKV scatter into g-layout [3][win][head][n][d], q pre-scaled by SCALEQ
//  EPI 1: proj: window-reverse + unshift row remap, C[dst] = res[dst] + val
//  EPI 2: GELU (exact)
//  EPI 3: C[row,col] = res[row,col] + val
template<int EPI>
__global__ void __launch_bounds__(256) gemm_k(const float* __restrict__ A,
                                              const float* __restrict__ W,
                                              const float* __restrict__ bias,
                                              float* __restrict__ C,
                                              const float* __restrict__ res,
                                              int N, int K) {
    __shared__ float As[16][64];
    __shared__ float Bs[16][64];

    const int rowBase = blockIdx.y * 64;
    const int colBase = blockIdx.x * 64;
    const int t  = threadIdx.x;
    const int tx = t & 15;
    const int ty = t >> 4;

    const int arow = t >> 2,  acol = (t & 3)  << 2;
    const int brow = t >> 4,  bcol = (t & 15) << 2;

    float acc[4][4] = {};

    for (int k0 = 0; k0 < K; k0 += 16) {
        float4 a = *(const float4*)(A + (size_t)(rowBase + arow) * K + k0 + acol);
        As[acol + 0][arow] = a.x;
        As[acol + 1][arow] = a.y;
        As[acol + 2][arow] = a.z;
        As[acol + 3][arow] = a.w;
        *(float4*)&Bs[brow][bcol] =
            *(const float4*)(W + (size_t)(k0 + brow) * N + colBase + bcol);
        __syncthreads();
#pragma unroll
        for (int k = 0; k < 16; k++) {
            float4 av = *(const float4*)&As[k][ty << 2];
            float4 bv = *(const float4*)&Bs[k][tx << 2];
            float ar[4] = {av.x, av.y, av.z, av.w};
            float br[4] = {bv.x, bv.y, bv.z, bv.w};
#pragma unroll
            for (int i = 0; i < 4; i++)
#pragma unroll
                for (int j = 0; j < 4; j++)
                    acc[i][j] = fmaf(ar[i], br[j], acc[i][j]);
        }
        __syncthreads();
    }

#pragma unroll
    for (int i = 0; i < 4; i++) {
        int row = rowBase + (ty << 2) + i;

        // row remap (only needed by EPI 0/1)
        int win = 0, n = 0;
        size_t dstrow = 0;
        if (EPI == 0 || EPI == 1) {
            win = row / NT; n = row % NT;
        }
        if (EPI == 1) {
            int b = win >> 6, wrem = win & 63;
            int ii = (wrem >> 3) * WSZ + n / WSZ;
            int jj = (wrem & 7)  * WSZ + n % WSZ;
            int h = ii + SSH; if (h >= Hh) h -= Hh;
            int w = jj + SSH; if (w >= Wd) w -= Wd;
            dstrow = (size_t)b * (Hh * Wd) + h * Wd + w;
        }

#pragma unroll
        for (int j = 0; j < 4; j++) {
            int col  = colBase + (tx << 2) + j;
            float val = acc[i][j] + bias[col];

            if (EPI == 0) {
                int three = col / Cc;
                int rem   = col % Cc;
                int head  = rem >> 5;
                int d     = rem & 31;
                if (three == 0) val *= SCALEQ;
                size_t idx = ((((size_t)three * NWINTOT + win) * NHEADS + head) * NT + n) * HDm + d;
                C[idx] = val;
            } else if (EPI == 1) {
                size_t idx = dstrow * Cc + col;
                C[idx] = res[idx] + val;
            } else if (EPI == 2) {
                C[(size_t)row * N + col] = 0.5f * val * (1.0f + erff(val * 0.70710678118654752f));
            } else {
                size_t idx = (size_t)row * N + col;
                C[idx] = res[idx] + val;
            }
        }
    }
}

// ---------------- attention: one block per (window, head) ----------------
__global__ void __launch_bounds__(256) attn_kernel(const float* __restrict__ qkv,
                                                   const float* __restrict__ mask,
                                                   const float* __restrict__ rel_table,
                                                   float* __restrict__ out) {
    __shared__ float sq[NT * HDm];
    __shared__ float sk[NT * HDm];
    __shared__ float sv[NT * HDm];
    __shared__ float ss[NT * 50];

    const int win  = blockIdx.x / NHEADS;
    const int head = blockIdx.x % NHEADS;

    const size_t stride3 = (size_t)NWINTOT * NHEADS * NT * HDm;
    const size_t base    = ((size_t)win * NHEADS + head) * NT * HDm;
    const float* qp = qkv + base;
    const float* kp = qkv + stride3 + base;
    const float* vp = qkv + 2 * stride3 + base;

    for (int i = threadIdx.x; i < NT * HDm; i += 256) {
        sq[i] = qp[i];
        sk[i] = kp[i];
        sv[i] = vp[i];
    }
    __syncthreads();

    const int wrem = win & 63;
    const float* mp = mask + (size_t)wrem * NT * NT;

    for (int idx = threadIdx.x; idx < NT * NT; idx += 256) {
        int n = idx / NT, m = idx % NT;
        float d = 0.f;
#pragma unroll
        for (int k = 0; k < HDm; k++)
            d = fmaf(sq[n * HDm + k], sk[m * HDm + k], d);
        int rel = (n / WSZ - m / WSZ + (WSZ - 1)) * (2 * WSZ - 1)
                + (n % WSZ - m % WSZ + (WSZ - 1));
        ss[n * 50 + m] = d + rel_table[rel * NHEADS + head] + mp[idx];
    }
    __syncthreads();

    // softmax: warp per row
    const int lane = threadIdx.x & 31;
    const int wid  = threadIdx.x >> 5;
    for (int n = wid; n < NT; n += 8) {
        float* r = ss + n * 50;
        float a  = (lane < NT)      ? r[lane]      : -1e30f;
        float b2 = (lane + 32 < NT) ? r[lane + 32] : -1e30f;
        float mx = fmaxf(a, b2);
#pragma unroll
        for (int o = 16; o > 0; o >>= 1) mx = fmaxf(mx, __shfl_xor_sync(0xFFFFFFFFu, mx, o));
        float e1 = (lane < NT)      ? __expf(a  - mx) : 0.f;
        float e2 = (lane + 32 < NT) ? __expf(b2 - mx) : 0.f;
        float s = e1 + e2;
#pragma unroll
        for (int o = 16; o > 0; o >>= 1) s += __shfl_xor_sync(0xFFFFFFFFu, s, o);
        float inv = 1.0f / s;
        if (lane < NT)      r[lane]      = e1 * inv;
        if (lane + 32 < NT) r[lane + 32] = e2 * inv;
    }
    __syncthreads();

    for (int idx = threadIdx.x; idx < NT * HDm; idx += 256) {
        int n = idx >> 5, d = idx & 31;
        float acc = 0.f;
#pragma unroll
        for (int m = 0; m < NT; m++)
            acc = fmaf(ss[n * 50 + m], sv[m * HDm + d], acc);
        out[((size_t)win * NT + n) * Cc + head * HDm + d] = acc;
    }
}

// ---------------- launch ----------------
extern "C" void kernel_launch(void* const* d_in, const int* in_sizes, int n_in,
                              void* d_out, int out_size) {
    const float* x       = (const float*)d_in[0];
    const float* mask    = (const float*)d_in[1];
    const float* rel_tab = (const float*)d_in[2];
    const float* qkv_w   = (const float*)d_in[3];
    const float* qkv_b   = (const float*)d_in[4];
    const float* proj_w  = (const float*)d_in[5];
    const float* proj_b  = (const float*)d_in[6];
    const float* n1_w    = (const float*)d_in[7];
    const float* n1_b    = (const float*)d_in[8];
    const float* n2_w    = (const float*)d_in[9];
    const float* n2_b    = (const float*)d_in[10];
    const float* fc1_w   = (const float*)d_in[11];
    const float* fc1_b   = (const float*)d_in[12];
    const float* fc2_w   = (const float*)d_in[13];
    const float* fc2_b   = (const float*)d_in[14];
    float* out = (float*)d_out;

    float *xw, *qkv, *attn, *xres, *h2, *hidden;
    cudaGetSymbolAddress((void**)&xw,     g_xw);
    cudaGetSymbolAddress((void**)&qkv,    g_qkv);
    cudaGetSymbolAddress((void**)&attn,   g_attn);
    cudaGetSymbolAddress((void**)&xres,   g_xres);
    cudaGetSymbolAddress((void**)&h2,     g_h2);
    cudaGetSymbolAddress((void**)&hidden, g_hidden);

    const int MB = M_TOK / 64;   // 1568

    // 1. LN1 + shift + window partition
    ln_kernel<1><<<M_TOK / 8, 256>>>(x, n1_w, n1_b, xw);
    // 2. QKV GEMM with scatter epilogue (q pre-scaled)
    gemm_k<0><<<dim3(3 * Cc / 64, MB), 256>>>(xw, qkv_w, qkv_b, qkv, nullptr, 3 * Cc, Cc);
    // 3. windowed attention
    attn_kernel<<<NWINTOT * NHEADS, 256>>>(qkv, mask, rel_tab, attn);
    // 4. proj GEMM + window reverse + unshift + residual
    gemm_k<1><<<dim3(Cc / 64, MB), 256>>>(attn, proj_w, proj_b, xres, x, Cc, Cc);
    // 5. LN2
    ln_kernel<0><<<M_TOK / 8, 256>>>(xres, n2_w, n2_b, h2);
    // 6. FC1 + GELU
    gemm_k<2><<<dim3(HIDDEN / 64, MB), 256>>>(h2, fc1_w, fc1_b, hidden, nullptr, HIDDEN, Cc);
    // 7. FC2 + residual -> output
    gemm_k<3><<<dim3(Cc / 64, MB), 256>>>(hidden, fc2_w, fc2_b, out, xres, Cc, HIDDEN);
}

// round 2
// speedup vs baseline: 2.2726x; 2.2726x over previous
#include <cuda_runtime.h>
#include <math.h>
#include <stdint.h>

// ---------------- problem constants ----------------
#define Bq      32
#define Hh      56
#define Wd      56
#define Cc      192
#define WSZ     7
#define SSH     3
#define NHEADS  6
#define HDm     32
#define NT      49          // tokens per window
#define NWIN    64          // windows per image
#define HIDDEN  768
#define M_TOK   (Bq*Hh*Wd)  // 100352
#define NWINTOT (Bq*NWIN)   // 2048
#define SCALEQ  0.17677669529663687f
#define EPSLN   1e-5f

// ---------------- scratch (device globals; allocation is forbidden) ----------
__device__ __align__(256) float g_xw    [M_TOK * Cc];
__device__ __align__(256) float g_qkv   [3u * NWINTOT * NHEADS * NT * HDm];
__device__ __align__(256) float g_attn  [M_TOK * Cc];
__device__ __align__(256) float g_xres  [M_TOK * Cc];
__device__ __align__(256) float g_h2    [M_TOK * Cc];
__device__ __align__(256) float g_hidden[M_TOK * HIDDEN];
// transposed weights: qkvT (576x192), projT (192x192), fc1T (768x192), fc2T (192x768)
__device__ __align__(256) float g_wT    [576*192 + 192*192 + 768*192 + 192*768];
#define OFF_QKVT 0
#define OFF_PROJT (576*192)
#define OFF_FC1T (OFF_PROJT + 192*192)
#define OFF_FC2T (OFF_FC1T + 768*192)

// ---------------- helpers ----------------
__device__ __forceinline__ float to_tf32(float x) {
    uint32_t u;
    asm("cvt.rna.tf32.f32 %0, %1;" : "=r"(u) : "f"(x));
    return __uint_as_float(u);
}

__device__ __forceinline__ void mma_tf32(float* d, const float* a, const float* b) {
    asm volatile(
        "mma.sync.aligned.m16n8k8.row.col.f32.tf32.tf32.f32 "
        "{%0,%1,%2,%3},{%4,%5,%6,%7},{%8,%9},{%0,%1,%2,%3};\n"
        : "+f"(d[0]), "+f"(d[1]), "+f"(d[2]), "+f"(d[3])
        : "r"(__float_as_uint(a[0])), "r"(__float_as_uint(a[1])),
          "r"(__float_as_uint(a[2])), "r"(__float_as_uint(a[3])),
          "r"(__float_as_uint(b[0])), "r"(__float_as_uint(b[1])));
}

// ---------------- weight transpose: WT[n][k] = W[k][n] ----------------
__global__ void __launch_bounds__(256) transpose_k(const float* __restrict__ W,
                                                   float* __restrict__ WT,
                                                   int K, int N) {
    __shared__ float tile[32][33];
    int nb = blockIdx.x * 32, kb = blockIdx.y * 32;
    int tx = threadIdx.x, ty = threadIdx.y;
#pragma unroll
    for (int j = 0; j < 32; j += 8)
        tile[ty + j][tx] = W[(size_t)(kb + ty + j) * N + nb + tx];
    __syncthreads();
#pragma unroll
    for (int j = 0; j < 32; j += 8)
        WT[(size_t)(nb + ty + j) * K + kb + tx] = tile[tx][ty + j];
}

// ---------------- LayerNorm (warp per row) ----------------
template<int WINDOWED>
__global__ void __launch_bounds__(256) ln_kernel(const float* __restrict__ x,
                                                 const float* __restrict__ gma,
                                                 const float* __restrict__ bta,
                                                 float* __restrict__ out) {
    int row  = blockIdx.x * 8 + (threadIdx.x >> 5);
    int lane = threadIdx.x & 31;
    if (row >= M_TOK) return;

    int src;
    if (WINDOWED) {
        int win = row / NT, n = row % NT;
        int b = win >> 6, wrem = win & 63;
        int i = (wrem >> 3) * WSZ + n / WSZ;
        int j = (wrem & 7)  * WSZ + n % WSZ;
        int h = i + SSH; if (h >= Hh) h -= Hh;
        int w = j + SSH; if (w >= Wd) w -= Wd;
        src = b * (Hh * Wd) + h * Wd + w;
    } else {
        src = row;
    }

    const float* xp = x + (size_t)src * Cc;
    float v[6];
    float s = 0.f, s2 = 0.f;
#pragma unroll
    for (int t = 0; t < 6; t++) {
        v[t] = xp[lane + 32 * t];
        s  += v[t];
        s2 += v[t] * v[t];
    }
#pragma unroll
    for (int o = 16; o > 0; o >>= 1) {
        s  += __shfl_xor_sync(0xFFFFFFFFu, s,  o);
        s2 += __shfl_xor_sync(0xFFFFFFFFu, s2, o);
    }
    float m   = s * (1.0f / Cc);
    float var = s2 * (1.0f / Cc) - m * m;
    float r   = rsqrtf(var + EPSLN);

    float* op = out + (size_t)row * Cc;
#pragma unroll
    for (int t = 0; t < 6; t++) {
        int c = lane + 32 * t;
        op[c] = (v[t] - m) * r * gma[c] + bta[c];
    }
}

// ---------------- tf32 tensor-core GEMM, 128x64 tile, BK=16 ----------------
// C = A[M x K] * W[K x N] + bias, W supplied transposed as WT[N x K].
// Epilogues:
//  EPI 0: QKV scatter into [3][win][head][n][d], q pre-scaled by SCALEQ
//  EPI 1: proj: window-reverse + unshift row remap, C[dst] = res[dst] + val
//  EPI 2: GELU (exact)
//  EPI 3: C[row,col] = res[row,col] + val
#define GST 20   // smem row stride (20 mod 32 => conflict-free fragment LDS)

template<int EPI>
__global__ void __launch_bounds__(256) gemm_tc(const float* __restrict__ A,
                                               const float* __restrict__ WT,
                                               const float* __restrict__ bias,
                                               float* __restrict__ C,
                                               const float* __restrict__ res,
                                               int N, int K) {
    __shared__ float As[2][128 * GST];
    __shared__ float Bs[2][64 * GST];

    const int t    = threadIdx.x;
    const int lane = t & 31, warp = t >> 5;
    const int g    = lane >> 2, tg = lane & 3;
    const int wm   = warp >> 1, wn = warp & 1;
    const int rowBase = blockIdx.y * 128, colBase = blockIdx.x * 64;

    const int aRow = t >> 2;              // 0..63 (+64 for second half)
    const int aKq  = (t & 3) * 4;
    const int bRow = t >> 2;              // 0..63
    const int bKq  = (t & 3) * 4;

    const int KT = K >> 4;

    const float* Ap0 = A  + (size_t)(rowBase + aRow)      * K + aKq;
    const float* Ap1 = A  + (size_t)(rowBase + aRow + 64) * K + aKq;
    const float* Bp  = WT + (size_t)(colBase + bRow)      * K + bKq;

    float4 pa0 = *(const float4*)Ap0;
    float4 pa1 = *(const float4*)Ap1;
    float4 pb  = *(const float4*)Bp;

    float acc[2][4][4];
#pragma unroll
    for (int i = 0; i < 2; i++)
#pragma unroll
        for (int j = 0; j < 4; j++)
#pragma unroll
            for (int k = 0; k < 4; k++) acc[i][j][k] = 0.f;

    // store tile 0 (converted to tf32)
    {
        float* a0 = &As[0][aRow * GST + aKq];
        a0[0] = to_tf32(pa0.x); a0[1] = to_tf32(pa0.y); a0[2] = to_tf32(pa0.z); a0[3] = to_tf32(pa0.w);
        float* a1 = &As[0][(aRow + 64) * GST + aKq];
        a1[0] = to_tf32(pa1.x); a1[1] = to_tf32(pa1.y); a1[2] = to_tf32(pa1.z); a1[3] = to_tf32(pa1.w);
        float* b0 = &Bs[0][bRow * GST + bKq];
        b0[0] = to_tf32(pb.x);  b0[1] = to_tf32(pb.y);  b0[2] = to_tf32(pb.z);  b0[3] = to_tf32(pb.w);
    }
    __syncthreads();

    for (int kt = 0; kt < KT; kt++) {
        const int buf = kt & 1;
        if (kt + 1 < KT) {
            int ko = (kt + 1) * 16;
            pa0 = *(const float4*)(Ap0 + ko);
            pa1 = *(const float4*)(Ap1 + ko);
            pb  = *(const float4*)(Bp  + ko);
        }

#pragma unroll
        for (int ks = 0; ks < 16; ks += 8) {
            float a[2][4], b[4][2];
#pragma unroll
            for (int mt = 0; mt < 2; mt++) {
                int rb = (wm * 32 + mt * 16 + g) * GST + ks + tg;
                a[mt][0] = As[buf][rb];
                a[mt][1] = As[buf][rb + 8 * GST];
                a[mt][2] = As[buf][rb + 4];
                a[mt][3] = As[buf][rb + 8 * GST + 4];
            }
#pragma unroll
            for (int nt = 0; nt < 4; nt++) {
                int rb = (wn * 32 + nt * 8 + g) * GST + ks + tg;
                b[nt][0] = Bs[buf][rb];
                b[nt][1] = Bs[buf][rb + 4];
            }
#pragma unroll
            for (int mt = 0; mt < 2; mt++)
#pragma unroll
                for (int nt = 0; nt < 4; nt++)
                    mma_tf32(acc[mt][nt], a[mt], b[nt]);
        }

        if (kt + 1 < KT) {
            const int nb = buf ^ 1;
            float* a0 = &As[nb][aRow * GST + aKq];
            a0[0] = to_tf32(pa0.x); a0[1] = to_tf32(pa0.y); a0[2] = to_tf32(pa0.z); a0[3] = to_tf32(pa0.w);
            float* a1 = &As[nb][(aRow + 64) * GST + aKq];
            a1[0] = to_tf32(pa1.x); a1[1] = to_tf32(pa1.y); a1[2] = to_tf32(pa1.z); a1[3] = to_tf32(pa1.w);
            float* b0 = &Bs[nb][bRow * GST + bKq];
            b0[0] = to_tf32(pb.x);  b0[1] = to_tf32(pb.y);  b0[2] = to_tf32(pb.z);  b0[3] = to_tf32(pb.w);
        }
        __syncthreads();
    }

    // ---------------- epilogue ----------------
#pragma unroll
    for (int mt = 0; mt < 2; mt++) {
#pragma unroll
        for (int rs = 0; rs < 2; rs++) {
            int row = rowBase + wm * 32 + mt * 16 + g + rs * 8;

            int win = 0, n = 0;
            size_t dstrow = 0;
            if (EPI == 0 || EPI == 1) { win = row / NT; n = row % NT; }
            if (EPI == 1) {
                int b = win >> 6, wrem = win & 63;
                int ii = (wrem >> 3) * WSZ + n / WSZ;
                int jj = (wrem & 7)  * WSZ + n % WSZ;
                int h = ii + SSH; if (h >= Hh) h -= Hh;
                int w = jj + SSH; if (w >= Wd) w -= Wd;
                dstrow = (size_t)b * (Hh * Wd) + h * Wd + w;
            }

#pragma unroll
            for (int nt = 0; nt < 4; nt++) {
#pragma unroll
                for (int c = 0; c < 2; c++) {
                    int col = colBase + wn * 32 + nt * 8 + 2 * tg + c;
                    float val = acc[mt][nt][rs * 2 + c] + bias[col];

                    if (EPI == 0) {
                        int three = col / Cc;
                        int rem   = col % Cc;
                        int head  = rem >> 5;
                        int d     = rem & 31;
                        if (three == 0) val *= SCALEQ;
                        size_t idx = ((((size_t)three * NWINTOT + win) * NHEADS + head) * NT + n) * HDm + d;
                        C[idx] = val;
                    } else if (EPI == 1) {
                        size_t idx = dstrow * Cc + col;
                        C[idx] = res[idx] + val;
                    } else if (EPI == 2) {
                        C[(size_t)row * N + col] = 0.5f * val * (1.0f + erff(val * 0.70710678118654752f));
                    } else {
                        size_t idx = (size_t)row * N + col;
                        C[idx] = res[idx] + val;
                    }
                }
            }
        }
    }
}

// ---------------- attention: one block per (window, head) ----------------
#define QST 36   // padded row stride for q/k/v tiles
__global__ void __launch_bounds__(256) attn_kernel(const float* __restrict__ qkv,
                                                   const float* __restrict__ mask,
                                                   const float* __restrict__ rel_table,
                                                   float* __restrict__ out) {
    __shared__ float sq[NT * QST];
    __shared__ float sk[NT * QST];
    __shared__ float sv[NT * QST];
    __shared__ float ss[NT * 50];

    const int win  = blockIdx.x / NHEADS;
    const int head = blockIdx.x % NHEADS;

    const size_t stride3 = (size_t)NWINTOT * NHEADS * NT * HDm;
    const size_t base    = ((size_t)win * NHEADS + head) * NT * HDm;
    const float* qp = qkv + base;
    const float* kp = qkv + stride3 + base;
    const float* vp = qkv + 2 * stride3 + base;

    for (int i = threadIdx.x; i < NT * HDm; i += 256) {
        int n = i >> 5, d = i & 31;
        sq[n * QST + d] = qp[i];
        sk[n * QST + d] = kp[i];
        sv[n * QST + d] = vp[i];
    }
    __syncthreads();

    const int wrem = win & 63;
    const float* mp = mask + (size_t)wrem * NT * NT;

    for (int idx = threadIdx.x; idx < NT * NT; idx += 256) {
        int n = idx / NT, m = idx - n * NT;
        const float4* q4 = (const float4*)(sq + n * QST);
        const float4* k4 = (const float4*)(sk + m * QST);
        float d = 0.f;
#pragma unroll
        for (int k = 0; k < 8; k++) {
            float4 a = q4[k], b = k4[k];
            d = fmaf(a.x, b.x, d);
            d = fmaf(a.y, b.y, d);
            d = fmaf(a.z, b.z, d);
            d = fmaf(a.w, b.w, d);
        }
        int rel = (n / WSZ - m / WSZ + (WSZ - 1)) * (2 * WSZ - 1)
                + (n % WSZ - m % WSZ + (WSZ - 1));
        ss[n * 50 + m] = d + rel_table[rel * NHEADS + head] + mp[idx];
    }
    __syncthreads();

    // softmax: warp per row
    const int lane = threadIdx.x & 31;
    const int wid  = threadIdx.x >> 5;
    for (int n = wid; n < NT; n += 8) {
        float* r = ss + n * 50;
        float a  = (lane < NT)      ? r[lane]      : -1e30f;
        float b2 = (lane + 32 < NT) ? r[lane + 32] : -1e30f;
        float mx = fmaxf(a, b2);
#pragma unroll
        for (int o = 16; o > 0; o >>= 1) mx = fmaxf(mx, __shfl_xor_sync(0xFFFFFFFFu, mx, o));
        float e1 = (lane < NT)      ? __expf(a  - mx) : 0.f;
        float e2 = (lane + 32 < NT) ? __expf(b2 - mx) : 0.f;
        float s = e1 + e2;
#pragma unroll
        for (int o = 16; o > 0; o >>= 1) s += __shfl_xor_sync(0xFFFFFFFFu, s, o);
        float inv = 1.0f / s;
        if (lane < NT)      r[lane]      = e1 * inv;
        if (lane + 32 < NT) r[lane + 32] = e2 * inv;
    }
    __syncthreads();

    for (int idx = threadIdx.x; idx < NT * HDm; idx += 256) {
        int n = idx >> 5, d = idx & 31;
        float acc = 0.f;
#pragma unroll
        for (int m = 0; m < NT; m++)
            acc = fmaf(ss[n * 50 + m], sv[m * QST + d], acc);
        out[((size_t)win * NT + n) * Cc + head * HDm + d] = acc;
    }
}

// ---------------- launch ----------------
extern "C" void kernel_launch(void* const* d_in, const int* in_sizes, int n_in,
                              void* d_out, int out_size) {
    const float* x       = (const float*)d_in[0];
    const float* mask    = (const float*)d_in[1];
    const float* rel_tab = (const float*)d_in[2];
    const float* qkv_w   = (const float*)d_in[3];
    const float* qkv_b   = (const float*)d_in[4];
    const float* proj_w  = (const float*)d_in[5];
    const float* proj_b  = (const float*)d_in[6];
    const float* n1_w    = (const float*)d_in[7];
    const float* n1_b    = (const float*)d_in[8];
    const float* n2_w    = (const float*)d_in[9];
    const float* n2_b    = (const float*)d_in[10];
    const float* fc1_w   = (const float*)d_in[11];
    const float* fc1_b   = (const float*)d_in[12];
    const float* fc2_w   = (const float*)d_in[13];
    const float* fc2_b   = (const float*)d_in[14];
    float* out = (float*)d_out;

    float *xw, *qkv, *attn, *xres, *h2, *hidden, *wT;
    cudaGetSymbolAddress((void**)&xw,     g_xw);
    cudaGetSymbolAddress((void**)&qkv,    g_qkv);
    cudaGetSymbolAddress((void**)&attn,   g_attn);
    cudaGetSymbolAddress((void**)&xres,   g_xres);
    cudaGetSymbolAddress((void**)&h2,     g_h2);
    cudaGetSymbolAddress((void**)&hidden, g_hidden);
    cudaGetSymbolAddress((void**)&wT,     g_wT);

    float* qkvT = wT + OFF_QKVT;
    float* projT = wT + OFF_PROJT;
    float* fc1T  = wT + OFF_FC1T;
    float* fc2T  = wT + OFF_FC2T;

    dim3 tb(32, 8);
    transpose_k<<<dim3(576/32, 192/32), tb>>>(qkv_w,  qkvT, 192, 576);
    transpose_k<<<dim3(192/32, 192/32), tb>>>(proj_w, projT, 192, 192);
    transpose_k<<<dim3(768/32, 192/32), tb>>>(fc1_w,  fc1T, 192, 768);
    transpose_k<<<dim3(192/32, 768/32), tb>>>(fc2_w,  fc2T, 768, 192);

    const int MB = M_TOK / 128;  // 784

    // 1. LN1 + shift + window partition
    ln_kernel<1><<<M_TOK / 8, 256>>>(x, n1_w, n1_b, xw);
    // 2. QKV GEMM with scatter epilogue (q pre-scaled)
    gemm_tc<0><<<dim3(576/64, MB), 256>>>(xw, qkvT, qkv_b, qkv, nullptr, 576, 192);
    // 3. windowed attention
    attn_kernel<<<NWINTOT * NHEADS, 256>>>(qkv, mask, rel_tab, attn);
    // 4. proj GEMM + window reverse + unshift + residual
    gemm_tc<1><<<dim3(192/64, MB), 256>>>(attn, projT, proj_b, xres, x, 192, 192);
    // 5. LN2
    ln_kernel<0><<<M_TOK / 8, 256>>>(xres, n2_w, n2_b, h2);
    // 6. FC1 + GELU
    gemm_tc<2><<<dim3(768/64, MB), 256>>>(h2, fc1T, fc1_b, hidden, nullptr, 768, 192);
    // 7. FC2 + residual -> output
    gemm_tc<3><<<dim3(192/64, MB), 256>>>(hidden, fc2T, fc2_b, out, xres, 192, 768);
}

// round 5
// speedup vs baseline: 2.9857x; 1.3137x over previous
#include <cuda_runtime.h>
#include <cuda_bf16.h>
#include <math.h>
#include <stdint.h>

// ---------------- problem constants ----------------
#define Bq      32
#define Hh      56
#define Wd      56
#define Cc      192
#define WSZ     7
#define SSH     3
#define NHEADS  6
#define HDm     32
#define NT      49          // tokens per window
#define NWIN    64          // windows per image
#define HIDDEN  768
#define M_TOK   (Bq*Hh*Wd)  // 100352
#define NWINTOT (Bq*NWIN)   // 2048
#define SCALEQ  0.17677669529663687f
#define EPSLN   1e-5f

typedef __nv_bfloat16 bf16;

// ---------------- scratch (device globals; allocation is forbidden) ----------
__device__ __align__(256) bf16  g_xw    [M_TOK * Cc];                    // LN1 windowed, bf16
__device__ __align__(256) bf16  g_qkv   [3u * NWINTOT * NHEADS * NT * HDm];
__device__ __align__(256) bf16  g_attn  [M_TOK * Cc];                    // attention out (windowed rows)
__device__ __align__(256) float g_xres  [M_TOK * Cc];                    // x + attn (fp32 trunk)
__device__ __align__(256) bf16  g_h2    [M_TOK * Cc];                    // LN2, bf16
__device__ __align__(256) bf16  g_hidden[M_TOK * HIDDEN];                // fc1+gelu, bf16
// transposed bf16 weights: qkvT (576x192), projT (192x192), fc1T (768x192), fc2T (192x768)
__device__ __align__(256) bf16  g_wT    [576*192 + 192*192 + 768*192 + 192*768];
#define OFF_QKVT  0
#define OFF_PROJT (576*192)
#define OFF_FC1T  (OFF_PROJT + 192*192)
#define OFF_FC2T  (OFF_FC1T + 768*192)

// ---------------- bf16 mma m16n8k16 ----------------
__device__ __forceinline__ void mma_bf16(float* d, const uint32_t* a, const uint32_t* b) {
    asm volatile(
        "mma.sync.aligned.m16n8k16.row.col.f32.bf16.bf16.f32 "
        "{%0,%1,%2,%3},{%4,%5,%6,%7},{%8,%9},{%0,%1,%2,%3};\n"
        : "+f"(d[0]), "+f"(d[1]), "+f"(d[2]), "+f"(d[3])
        : "r"(a[0]), "r"(a[1]), "r"(a[2]), "r"(a[3]),
          "r"(b[0]), "r"(b[1]));
}

// ---------------- weight transpose+convert: WT[n][k] = bf16(W[k][n]) ----------
__global__ void __launch_bounds__(256) transpose_k(const float* __restrict__ W,
                                                   bf16* __restrict__ WT,
                                                   int K, int N) {
    __shared__ float tile[32][33];
    int nb = blockIdx.x * 32, kb = blockIdx.y * 32;
    int tx = threadIdx.x, ty = threadIdx.y;
#pragma unroll
    for (int j = 0; j < 32; j += 8)
        tile[ty + j][tx] = W[(size_t)(kb + ty + j) * N + nb + tx];
    __syncthreads();
#pragma unroll
    for (int j = 0; j < 32; j += 8)
        WT[(size_t)(nb + ty + j) * K + kb + tx] = __float2bfloat16(tile[tx][ty + j]);
}

// ---------------- LayerNorm (warp per row), bf16 out ----------------
template<int WINDOWED>
__global__ void __launch_bounds__(256) ln_kernel(const float* __restrict__ x,
                                                 const float* __restrict__ gma,
                                                 const float* __restrict__ bta,
                                                 bf16* __restrict__ out) {
    int row  = blockIdx.x * 8 + (threadIdx.x >> 5);
    int lane = threadIdx.x & 31;
    if (row >= M_TOK) return;

    int src;
    if (WINDOWED) {
        int win = row / NT, n = row % NT;
        int b = win >> 6, wrem = win & 63;
        int i = (wrem >> 3) * WSZ + n / WSZ;
        int j = (wrem & 7)  * WSZ + n % WSZ;
        int h = i + SSH; if (h >= Hh) h -= Hh;
        int w = j + SSH; if (w >= Wd) w -= Wd;
        src = b * (Hh * Wd) + h * Wd + w;
    } else {
        src = row;
    }

    const float* xp = x + (size_t)src * Cc;
    float v[6];
    float s = 0.f, s2 = 0.f;
#pragma unroll
    for (int t = 0; t < 6; t++) {
        v[t] = xp[lane + 32 * t];
        s  += v[t];
        s2 += v[t] * v[t];
    }
#pragma unroll
    for (int o = 16; o > 0; o >>= 1) {
        s  += __shfl_xor_sync(0xFFFFFFFFu, s,  o);
        s2 += __shfl_xor_sync(0xFFFFFFFFu, s2, o);
    }
    float m   = s * (1.0f / Cc);
    float var = s2 * (1.0f / Cc) - m * m;
    float r   = rsqrtf(var + EPSLN);

    bf16* op = out + (size_t)row * Cc;
#pragma unroll
    for (int t = 0; t < 6; t++) {
        int c = lane + 32 * t;
        op[c] = __float2bfloat16((v[t] - m) * r * gma[c] + bta[c]);
    }
}

// ---------------- bf16 tensor GEMM, 128x64 tile, BK=32 ----------------
// C = A[M x K] * W[K x N] + bias, W given transposed bf16 WT[N x K].
//  EPI 0: QKV scatter bf16 into [3][win][head][n][d], q pre-scaled
//  EPI 1: proj: window-reverse + unshift row remap, fp32 out = res[dst] + val
//  EPI 2: GELU (exact), bf16 out
//  EPI 3: fp32 out[row,col] = res[row,col] + val
#define GST 40   // smem row stride in bf16 (20 words -> conflict-free)

template<int EPI>
__global__ void __launch_bounds__(256) gemm_bf(const bf16* __restrict__ A,
                                               const bf16* __restrict__ WT,
                                               const float* __restrict__ bias,
                                               void* __restrict__ Cv,
                                               const float* __restrict__ res,
                                               int N, int K) {
    __shared__ bf16 As[2][128 * GST];
    __shared__ bf16 Bs[2][64 * GST];

    const int t    = threadIdx.x;
    const int lane = t & 31, warp = t >> 5;
    const int g    = lane >> 2, tg = lane & 3;
    const int wm   = warp >> 1, wn = warp & 1;     // 4x2 warps, warp tile 32x32
    const int rowBase = blockIdx.y * 128, colBase = blockIdx.x * 64;

    const int ldRow  = t >> 2;          // 0..63
    const int ldChk  = (t & 3) * 8;     // bf16 offset of 16B chunk

    const int KT = K >> 5;

    const bf16* Ap0 = A  + (size_t)(rowBase + ldRow)      * K + ldChk;
    const bf16* Ap1 = A  + (size_t)(rowBase + ldRow + 64) * K + ldChk;
    const bf16* Bp  = WT + (size_t)(colBase + ldRow)      * K + ldChk;

    uint4 ra0 = *(const uint4*)Ap0;
    uint4 ra1 = *(const uint4*)Ap1;
    uint4 rb  = *(const uint4*)Bp;

    float acc[2][4][4];
#pragma unroll
    for (int i = 0; i < 2; i++)
#pragma unroll
        for (int j = 0; j < 4; j++)
#pragma unroll
            for (int k = 0; k < 4; k++) acc[i][j][k] = 0.f;

    *(uint4*)&As[0][ldRow * GST + ldChk]        = ra0;
    *(uint4*)&As[0][(ldRow + 64) * GST + ldChk] = ra1;
    *(uint4*)&Bs[0][ldRow * GST + ldChk]        = rb;
    __syncthreads();

    for (int kt = 0; kt < KT; kt++) {
        const int buf = kt & 1;
        if (kt + 1 < KT) {
            int ko = (kt + 1) * 32;
            ra0 = *(const uint4*)(Ap0 + ko);
            ra1 = *(const uint4*)(Ap1 + ko);
            rb  = *(const uint4*)(Bp  + ko);
        }

#pragma unroll
        for (int ks = 0; ks < 32; ks += 16) {
            uint32_t a[2][4], b[4][2];
#pragma unroll
            for (int mt = 0; mt < 2; mt++) {
                int r0 = (wm * 32 + mt * 16 + g) * GST;
                int r1 = r0 + 8 * GST;
                a[mt][0] = *(const uint32_t*)&As[buf][r0 + ks + 2 * tg];
                a[mt][1] = *(const uint32_t*)&As[buf][r1 + ks + 2 * tg];
                a[mt][2] = *(const uint32_t*)&As[buf][r0 + ks + 8 + 2 * tg];
                a[mt][3] = *(const uint32_t*)&As[buf][r1 + ks + 8 + 2 * tg];
            }
#pragma unroll
            for (int nt = 0; nt < 4; nt++) {
                int rbn = (wn * 32 + nt * 8 + g) * GST;
                b[nt][0] = *(const uint32_t*)&Bs[buf][rbn + ks + 2 * tg];
                b[nt][1] = *(const uint32_t*)&Bs[buf][rbn + ks + 8 + 2 * tg];
            }
#pragma unroll
            for (int mt = 0; mt < 2; mt++)
#pragma unroll
                for (int nt = 0; nt < 4; nt++)
                    mma_bf16(acc[mt][nt], a[mt], b[nt]);
        }

        if (kt + 1 < KT) {
            const int nb = buf ^ 1;
            *(uint4*)&As[nb][ldRow * GST + ldChk]        = ra0;
            *(uint4*)&As[nb][(ldRow + 64) * GST + ldChk] = ra1;
            *(uint4*)&Bs[nb][ldRow * GST + ldChk]        = rb;
        }
        __syncthreads();
    }

    // ---------------- epilogue ----------------
#pragma unroll
    for (int mt = 0; mt < 2; mt++) {
#pragma unroll
        for (int rs = 0; rs < 2; rs++) {
            int row = rowBase + wm * 32 + mt * 16 + g + rs * 8;

            int win = 0, n = 0;
            size_t dstrow = 0;
            if (EPI == 0 || EPI == 1) { win = row / NT; n = row % NT; }
            if (EPI == 1) {
                int b = win >> 6, wrem = win & 63;
                int ii = (wrem >> 3) * WSZ + n / WSZ;
                int jj = (wrem & 7)  * WSZ + n % WSZ;
                int h = ii + SSH; if (h >= Hh) h -= Hh;
                int w = jj + SSH; if (w >= Wd) w -= Wd;
                dstrow = (size_t)b * (Hh * Wd) + h * Wd + w;
            }

#pragma unroll
            for (int nt = 0; nt < 4; nt++) {
#pragma unroll
                for (int c = 0; c < 2; c++) {
                    int col = colBase + wn * 32 + nt * 8 + 2 * tg + c;
                    float val = acc[mt][nt][rs * 2 + c] + bias[col];

                    if (EPI == 0) {
                        int three = col / Cc;
                        int rem   = col % Cc;
                        int head  = rem >> 5;
                        int d     = rem & 31;
                        if (three == 0) val *= SCALEQ;
                        size_t idx = ((((size_t)three * NWINTOT + win) * NHEADS + head) * NT + n) * HDm + d;
                        ((bf16*)Cv)[idx] = __float2bfloat16(val);
                    } else if (EPI == 1) {
                        size_t idx = dstrow * Cc + col;
                        ((float*)Cv)[idx] = res[idx] + val;
                    } else if (EPI == 2) {
                        ((bf16*)Cv)[(size_t)row * N + col] =
                            __float2bfloat16(0.5f * val * (1.0f + erff(val * 0.70710678118654752f)));
                    } else {
                        size_t idx = (size_t)row * N + col;
                        ((float*)Cv)[idx] = res[idx] + val;
                    }
                }
            }
        }
    }
}

// ---------------- attention: one block per (window, head) ----------------
#define QST 36   // padded row stride for q/k/v tiles
__global__ void __launch_bounds__(256) attn_kernel(const bf16* __restrict__ qkv,
                                                   const float* __restrict__ mask,
                                                   const float* __restrict__ rel_table,
                                                   bf16* __restrict__ out) {
    __shared__ float sq[NT * QST];
    __shared__ float sk[NT * QST];
    __shared__ float sv[NT * QST];
    __shared__ float ss[NT * 50];

    const int win  = blockIdx.x / NHEADS;
    const int head = blockIdx.x % NHEADS;

    const size_t stride3 = (size_t)NWINTOT * NHEADS * NT * HDm;
    const size_t base    = ((size_t)win * NHEADS + head) * NT * HDm;
    const bf16* qp = qkv + base;
    const bf16* kp = qkv + stride3 + base;
    const bf16* vp = qkv + 2 * stride3 + base;

    for (int i = threadIdx.x; i < NT * HDm; i += 256) {
        int n = i >> 5, d = i & 31;
        sq[n * QST + d] = __bfloat162float(qp[i]);
        sk[n * QST + d] = __bfloat162float(kp[i]);
        sv[n * QST + d] = __bfloat162float(vp[i]);
    }
    __syncthreads();

    const int wrem = win & 63;
    const float* mp = mask + (size_t)wrem * NT * NT;

    for (int idx = threadIdx.x; idx < NT * NT; idx += 256) {
        int n = idx / NT, m = idx - n * NT;
        const float4* q4 = (const float4*)(sq + n * QST);
        const float4* k4 = (const float4*)(sk + m * QST);
        float d = 0.f;
#pragma unroll
        for (int k = 0; k < 8; k++) {
            float4 a = q4[k], b = k4[k];
            d = fmaf(a.x, b.x, d);
            d = fmaf(a.y, b.y, d);
            d = fmaf(a.z, b.z, d);
            d = fmaf(a.w, b.w, d);
        }
        int rel = (n / WSZ - m / WSZ + (WSZ - 1)) * (2 * WSZ - 1)
                + (n % WSZ - m % WSZ + (WSZ - 1));
        ss[n * 50 + m] = d + rel_table[rel * NHEADS + head] + mp[idx];
    }
    __syncthreads();

    // softmax: warp per row
    const int lane = threadIdx.x & 31;
    const int wid  = threadIdx.x >> 5;
    for (int n = wid; n < NT; n += 8) {
        float* r = ss + n * 50;
        float a  = (lane < NT)      ? r[lane]      : -1e30f;
        float b2 = (lane + 32 < NT) ? r[lane + 32] : -1e30f;
        float mx = fmaxf(a, b2);
#pragma unroll
        for (int o = 16; o > 0; o >>= 1) mx = fmaxf(mx, __shfl_xor_sync(0xFFFFFFFFu, mx, o));
        float e1 = (lane < NT)      ? __expf(a  - mx) : 0.f;
        float e2 = (lane + 32 < NT) ? __expf(b2 - mx) : 0.f;
        float s = e1 + e2;
#pragma unroll
        for (int o = 16; o > 0; o >>= 1) s += __shfl_xor_sync(0xFFFFFFFFu, s, o);
        float inv = 1.0f / s;
        if (lane < NT)      r[lane]      = e1 * inv;
        if (lane + 32 < NT) r[lane + 32] = e2 * inv;
    }
    __syncthreads();

    for (int idx = threadIdx.x; idx < NT * HDm; idx += 256) {
        int n = idx >> 5, d = idx & 31;
        float acc = 0.f;
#pragma unroll
        for (int m = 0; m < NT; m++)
            acc = fmaf(ss[n * 50 + m], sv[m * QST + d], acc);
        out[((size_t)win * NT + n) * Cc + head * HDm + d] = __float2bfloat16(acc);
    }
}

// ---------------- launch ----------------
extern "C" void kernel_launch(void* const* d_in, const int* in_sizes, int n_in,
                              void* d_out, int out_size) {
    const float* x       = (const float*)d_in[0];
    const float* mask    = (const float*)d_in[1];
    const float* rel_tab = (const float*)d_in[2];
    const float* qkv_w   = (const float*)d_in[3];
    const float* qkv_b   = (const float*)d_in[4];
    const float* proj_w  = (const float*)d_in[5];
    const float* proj_b  = (const float*)d_in[6];
    const float* n1_w    = (const float*)d_in[7];
    const float* n1_b    = (const float*)d_in[8];
    const float* n2_w    = (const float*)d_in[9];
    const float* n2_b    = (const float*)d_in[10];
    const float* fc1_w   = (const float*)d_in[11];
    const float* fc1_b   = (const float*)d_in[12];
    const float* fc2_w   = (const float*)d_in[13];
    const float* fc2_b   = (const float*)d_in[14];
    float* out = (float*)d_out;

    bf16 *xw, *qkv, *attn, *h2, *hidden, *wT;
    float *xres;
    cudaGetSymbolAddress((void**)&xw,     g_xw);
    cudaGetSymbolAddress((void**)&qkv,    g_qkv);
    cudaGetSymbolAddress((void**)&attn,   g_attn);
    cudaGetSymbolAddress((void**)&xres,   g_xres);
    cudaGetSymbolAddress((void**)&h2,     g_h2);
    cudaGetSymbolAddress((void**)&hidden, g_hidden);
    cudaGetSymbolAddress((void**)&wT,     g_wT);

    bf16* qkvT  = wT + OFF_QKVT;
    bf16* projT = wT + OFF_PROJT;
    bf16* fc1T  = wT + OFF_FC1T;
    bf16* fc2T  = wT + OFF_FC2T;

    dim3 tb(32, 8);
    transpose_k<<<dim3(576/32, 192/32), tb>>>(qkv_w,  qkvT, 192, 576);
    transpose_k<<<dim3(192/32, 192/32), tb>>>(proj_w, projT, 192, 192);
    transpose_k<<<dim3(768/32, 192/32), tb>>>(fc1_w,  fc1T, 192, 768);
    transpose_k<<<dim3(192/32, 768/32), tb>>>(fc2_w,  fc2T, 768, 192);

    const int MB = M_TOK / 128;  // 784

    // 1. LN1 + shift + window partition (bf16 out)
    ln_kernel<1><<<M_TOK / 8, 256>>>(x, n1_w, n1_b, xw);
    // 2. QKV GEMM with scatter epilogue (q pre-scaled), bf16 out
    gemm_bf<0><<<dim3(576/64, MB), 256>>>(xw, qkvT, qkv_b, qkv, nullptr, 576, 192);
    // 3. windowed attention (bf16 in/out, fp32 math)
    attn_kernel<<<NWINTOT * NHEADS, 256>>>(qkv, mask, rel_tab, attn);
    // 4. proj GEMM + window reverse + unshift + residual (fp32 out)
    gemm_bf<1><<<dim3(192/64, MB), 256>>>(attn, projT, proj_b, xres, x, 192, 192);
    // 5. LN2 (bf16 out)
    ln_kernel<0><<<M_TOK / 8, 256>>>(xres, n2_w, n2_b, h2);
    // 6. FC1 + GELU (bf16 out)
    gemm_bf<2><<<dim3(768/64, MB), 256>>>(h2, fc1T, fc1_b, hidden, nullptr, 768, 192);
    // 7. FC2 + residual -> output (fp32)
    gemm_bf<3><<<dim3(192/64, MB), 256>>>(hidden, fc2T, fc2_b, out, xres, 192, 768);
}